// round 1
// baseline (speedup 1.0000x reference)
#include <cuda_runtime.h>
#include <math.h>

#define N_NODES 20000
#define N_EDGES 320000
#define D 256
#define NADJ 4
#define LN_EPS 1e-5f

// ---------------- scratch (device globals; no allocation) ----------------
__device__ float g_h   [N_NODES * D];   // s0 = xW + b
__device__ float g_s1  [N_NODES * D];   // state 1
__device__ float g_s2  [N_NODES * D];   // state 2 (kernelA writes the s0-residual partial here)
__device__ float g_acc3[N_NODES * D];   // accumulated out-residual partials
__device__ int   g_counts[NADJ * N_NODES];
__device__ int   g_starts[NADJ * (N_NODES + 1)];
__device__ int   g_cursor[NADJ * N_NODES];
__device__ int2  g_perm  [NADJ * N_EDGES];     // (col, val-as-bits), CSR-permuted

// ---------------- CSR build ----------------
__global__ void zero_counts_kernel() {
    int i = blockIdx.x * blockDim.x + threadIdx.x;
    if (i < NADJ * N_NODES) g_counts[i] = 0;
}

__global__ void hist_kernel(const int* __restrict__ rows) {
    int total = NADJ * N_EDGES;
    for (int i = blockIdx.x * blockDim.x + threadIdx.x; i < total;
         i += gridDim.x * blockDim.x) {
        int a = i / N_EDGES;
        atomicAdd(&g_counts[a * N_NODES + rows[i]], 1);
    }
}

__global__ void scan_kernel() {
    // one block per adjacency, 1024 threads, chunked Hillis-Steele scan
    int a = blockIdx.x;
    const int* c = g_counts + a * N_NODES;
    int* s   = g_starts + a * (N_NODES + 1);
    int* cur = g_cursor + a * N_NODES;
    __shared__ int sd[1024];
    int t = threadIdx.x;
    int run = 0;
    for (int base = 0; base < N_NODES; base += 1024) {
        int idx = base + t;
        int v = (idx < N_NODES) ? c[idx] : 0;
        sd[t] = v;
        __syncthreads();
        #pragma unroll
        for (int off = 1; off < 1024; off <<= 1) {
            int x = (t >= off) ? sd[t - off] : 0;
            __syncthreads();
            sd[t] += x;
            __syncthreads();
        }
        int incl = sd[t];
        if (idx < N_NODES) {
            int ex = run + incl - v;
            s[idx] = ex;
            cur[idx] = ex;
        }
        int tot = sd[1023];
        __syncthreads();
        run += tot;
    }
    if (t == 0) s[N_NODES] = run;
}

__global__ void scatter_kernel(const int* __restrict__ rows,
                               const int* __restrict__ cols,
                               const float* __restrict__ vals) {
    int total = NADJ * N_EDGES;
    for (int i = blockIdx.x * blockDim.x + threadIdx.x; i < total;
         i += gridDim.x * blockDim.x) {
        int a = i / N_EDGES;
        int r = rows[i];
        int pos = atomicAdd(&g_cursor[a * N_NODES + r], 1);
        g_perm[a * N_EDGES + pos] = make_int2(cols[i], __float_as_int(vals[i]));
    }
}

// ---------------- GEMM: h = x @ W + b ----------------
#define BM 128
#define BN 128
#define BK 16
__global__ __launch_bounds__(256) void gemm_kernel(const float* __restrict__ X,
                                                   const float* __restrict__ W,
                                                   const float* __restrict__ bias) {
    __shared__ float As[BK][BM];
    __shared__ float Bs[BK][BN];
    int bm = blockIdx.x * BM;
    int bn = blockIdx.y * BN;
    int t  = threadIdx.x;
    int ty = t >> 4;        // 0..15
    int tx = t & 15;        // 0..15
    float acc[8][8];
    #pragma unroll
    for (int i = 0; i < 8; ++i)
        #pragma unroll
        for (int j = 0; j < 8; ++j) acc[i][j] = 0.f;

    for (int k0 = 0; k0 < D; k0 += BK) {
        // load A tile 128x16 (512 float4)
        #pragma unroll
        for (int l = 0; l < 2; ++l) {
            int idx = t + l * 256;
            int row = idx >> 2;
            int vec = idx & 3;
            float4 av = make_float4(0.f, 0.f, 0.f, 0.f);
            int gr = bm + row;
            if (gr < N_NODES)
                av = *reinterpret_cast<const float4*>(X + (size_t)gr * D + k0 + vec * 4);
            As[vec * 4 + 0][row] = av.x;
            As[vec * 4 + 1][row] = av.y;
            As[vec * 4 + 2][row] = av.z;
            As[vec * 4 + 3][row] = av.w;
        }
        // load B tile 16x128 (512 float4)
        #pragma unroll
        for (int l = 0; l < 2; ++l) {
            int idx = t + l * 256;
            int kr  = idx >> 5;
            int vec = idx & 31;
            float4 bv = *reinterpret_cast<const float4*>(W + (size_t)(k0 + kr) * D + bn + vec * 4);
            *reinterpret_cast<float4*>(&Bs[kr][vec * 4]) = bv;
        }
        __syncthreads();
        #pragma unroll
        for (int k = 0; k < BK; ++k) {
            float af[8], bf[8];
            #pragma unroll
            for (int i = 0; i < 8; ++i) af[i] = As[k][ty * 8 + i];
            #pragma unroll
            for (int j = 0; j < 8; ++j) bf[j] = Bs[k][tx * 8 + j];
            #pragma unroll
            for (int i = 0; i < 8; ++i)
                #pragma unroll
                for (int j = 0; j < 8; ++j) acc[i][j] += af[i] * bf[j];
        }
        __syncthreads();
    }
    #pragma unroll
    for (int i = 0; i < 8; ++i) {
        int gr = bm + ty * 8 + i;
        if (gr >= N_NODES) break;
        #pragma unroll
        for (int j = 0; j < 8; j += 4) {
            int gc = bn + tx * 8 + j;
            float4 o;
            o.x = acc[i][j + 0] + bias[gc + 0];
            o.y = acc[i][j + 1] + bias[gc + 1];
            o.z = acc[i][j + 2] + bias[gc + 2];
            o.w = acc[i][j + 3] + bias[gc + 3];
            *reinterpret_cast<float4*>(&g_h[(size_t)gr * D + gc]) = o;
        }
    }
}

// ---------------- fused SpMM gather kernels ----------------
// Each block owns one output row; 64 threads, each covers 4 consecutive dims.

__device__ __forceinline__ void gather_adj(int a, int row, int t, const float* __restrict__ src,
                                           int2* sbuf, float4& S) {
    int s = g_starts[a * (N_NODES + 1) + row];
    int e = g_starts[a * (N_NODES + 1) + row + 1];
    S = make_float4(0.f, 0.f, 0.f, 0.f);
    const float4* src4 = reinterpret_cast<const float4*>(src);
    for (int base = s; base < e; base += 64) {
        int m = min(64, e - base);
        if (t < m) sbuf[t] = g_perm[a * N_EDGES + base + t];
        __syncthreads();
        #pragma unroll 4
        for (int j = 0; j < m; ++j) {
            int2 cv = sbuf[j];
            float v = __int_as_float(cv.y);
            float4 hv = src4[(size_t)cv.x * 64 + t];
            S.x += v * hv.x; S.y += v * hv.y; S.z += v * hv.z; S.w += v * hv.w;
        }
        __syncthreads();
    }
}

__device__ __forceinline__ void fma4(float4& o, float w, const float4& S) {
    o.x += w * S.x; o.y += w * S.y; o.z += w * S.z; o.w += w * S.w;
}

// Kernel A: input s0=g_h. Produces s1, s2-partial (s0 residual), acc3-partial.
__global__ __launch_bounds__(64) void kernelA(const float* __restrict__ ws_seq_0,
                                              const float* __restrict__ ws_res_0,
                                              const float* __restrict__ ws_res_1) {
    int row = blockIdx.x;
    int t = threadIdx.x;
    const float k3 = 1.f / 3.f;
    float c0w[4] = { ws_seq_0[0] * k3, ws_seq_0[1] * k3, ws_seq_0[2] * k3, 0.f };
    float c1w[4] = { ws_res_0[0] * 0.25f, ws_res_0[1] * 0.25f, ws_res_0[2] * 0.25f, ws_res_0[3] * 0.25f };
    float c2w[4] = { ws_res_1[0] * k3, ws_res_1[1] * k3, 0.f, ws_res_1[2] * k3 };
    __shared__ int2 sbuf[64];
    float4 o0 = make_float4(0,0,0,0), o1 = o0, o2 = o0;
    #pragma unroll
    for (int a = 0; a < 4; ++a) {
        float4 S;
        gather_adj(a, row, t, g_h, sbuf, S);
        fma4(o0, c0w[a], S);
        fma4(o1, c1w[a], S);
        fma4(o2, c2w[a], S);
    }
    int off = row * 64 + t;
    reinterpret_cast<float4*>(g_s1)[off]   = o0;
    reinterpret_cast<float4*>(g_s2)[off]   = o1;
    reinterpret_cast<float4*>(g_acc3)[off] = o2;
}

// Kernel B: input s1. Finalizes s2, accumulates s1 residual into acc3.
__global__ __launch_bounds__(64) void kernelB(const float* __restrict__ ws_seq_0,
                                              const float* __restrict__ ws_res_1) {
    int row = blockIdx.x;
    int t = threadIdx.x;
    const float k3 = 1.f / 3.f;
    float c0w[4] = { ws_seq_0[3] * k3, ws_seq_0[4] * k3, ws_seq_0[5] * k3, 0.f };
    float c1w[4] = { ws_res_1[3] * k3, ws_res_1[4] * k3, 0.f, ws_res_1[5] * k3 };
    __shared__ int2 sbuf[64];
    int off = row * 64 + t;
    float4 prev2 = reinterpret_cast<const float4*>(g_s2)[off];
    float4 prev3 = reinterpret_cast<const float4*>(g_acc3)[off];
    float4 o0 = prev2, o1 = prev3;
    #pragma unroll
    for (int a = 0; a < 4; ++a) {
        float4 S;
        gather_adj(a, row, t, g_s1, sbuf, S);
        fma4(o0, c0w[a], S);
        fma4(o1, c1w[a], S);
    }
    reinterpret_cast<float4*>(g_s2)[off]   = o0;
    reinterpret_cast<float4*>(g_acc3)[off] = o1;
}

// Kernel C: input s2 (adjacencies 0,1). Adds acc3, then LayerNorm + exact GELU.
__global__ __launch_bounds__(64) void kernelC(const float* __restrict__ ws_seq_1,
                                              float* __restrict__ out) {
    int row = blockIdx.x;
    int t = threadIdx.x;
    float cw[2] = { ws_seq_1[0] * 0.5f, ws_seq_1[1] * 0.5f };
    __shared__ int2 sbuf[64];
    __shared__ float ssum[2], ssq[2];
    int off = row * 64 + t;
    float4 o = reinterpret_cast<const float4*>(g_acc3)[off];
    #pragma unroll
    for (int a = 0; a < 2; ++a) {
        float4 S;
        gather_adj(a, row, t, g_s2, sbuf, S);
        fma4(o, cw[a], S);
    }
    // LayerNorm (no affine) over the 256-dim row
    float sum = o.x + o.y + o.z + o.w;
    float sq  = o.x * o.x + o.y * o.y + o.z * o.z + o.w * o.w;
    #pragma unroll
    for (int d = 16; d > 0; d >>= 1) {
        sum += __shfl_xor_sync(0xffffffffu, sum, d);
        sq  += __shfl_xor_sync(0xffffffffu, sq,  d);
    }
    int wid = t >> 5;
    if ((t & 31) == 0) { ssum[wid] = sum; ssq[wid] = sq; }
    __syncthreads();
    sum = ssum[0] + ssum[1];
    sq  = ssq[0]  + ssq[1];
    float mu  = sum * (1.f / 256.f);
    float var = sq * (1.f / 256.f) - mu * mu;
    float inv = rsqrtf(var + LN_EPS);
    float4 r;
    {
        float y;
        y = (o.x - mu) * inv; r.x = 0.5f * y * (1.f + erff(y * 0.70710678118654752f));
        y = (o.y - mu) * inv; r.y = 0.5f * y * (1.f + erff(y * 0.70710678118654752f));
        y = (o.z - mu) * inv; r.z = 0.5f * y * (1.f + erff(y * 0.70710678118654752f));
        y = (o.w - mu) * inv; r.w = 0.5f * y * (1.f + erff(y * 0.70710678118654752f));
    }
    reinterpret_cast<float4*>(out)[off] = r;
}

// ---------------- launch ----------------
extern "C" void kernel_launch(void* const* d_in, const int* in_sizes, int n_in,
                              void* d_out, int out_size) {
    const float* x        = (const float*)d_in[0];
    const int*   rows     = (const int*)  d_in[1];
    const int*   cols     = (const int*)  d_in[2];
    const float* vals     = (const float*)d_in[3];
    const float* W        = (const float*)d_in[4];
    const float* b        = (const float*)d_in[5];
    const float* ws_seq_0 = (const float*)d_in[6];
    const float* ws_seq_1 = (const float*)d_in[7];
    const float* ws_res_0 = (const float*)d_in[8];
    const float* ws_res_1 = (const float*)d_in[9];
    float* out = (float*)d_out;

    zero_counts_kernel<<<(NADJ * N_NODES + 255) / 256, 256>>>();
    hist_kernel<<<592, 256>>>(rows);
    scan_kernel<<<4, 1024>>>();
    scatter_kernel<<<592, 256>>>(rows, cols, vals);
    gemm_kernel<<<dim3((N_NODES + BM - 1) / BM, D / BN), 256>>>(x, W, b);
    kernelA<<<N_NODES, 64>>>(ws_seq_0, ws_res_0, ws_res_1);
    kernelB<<<N_NODES, 64>>>(ws_seq_0, ws_res_1);
    kernelC<<<N_NODES, 64>>>(ws_seq_1, out);
}

// round 2
// speedup vs baseline: 1.3093x; 1.3093x over previous
#include <cuda_runtime.h>
#include <cuda_fp16.h>
#include <math.h>

#define N_NODES 20000
#define N_EDGES 320000
#define D 256
#define NADJ 4
#define LN_EPS 1e-5f

// ---------------- scratch (device globals; no allocation) ----------------
__device__ __half2 g_h16 [N_NODES * 128];   // s0 = xW + b   (fp16)
__device__ __half2 g_s116[N_NODES * 128];   // state 1       (fp16)
__device__ __half2 g_s216[N_NODES * 128];   // state 2 final (fp16)
__device__ float   g_s2f [N_NODES * D];     // s2 fp32 partial (s0 residual)
__device__ float   g_acc3[N_NODES * D];     // out-residual fp32 accumulator
__device__ int     g_counts[NADJ * N_NODES];
__device__ int     g_starts[NADJ * (N_NODES + 1)];
__device__ int     g_cursor[NADJ * N_NODES];
__device__ int2    g_perm  [NADJ * N_EDGES];   // (col, val-as-bits), CSR-permuted

// ---------------- CSR build ----------------
__global__ void zero_counts_kernel() {
    int i = blockIdx.x * blockDim.x + threadIdx.x;
    if (i < NADJ * N_NODES) g_counts[i] = 0;
}

__global__ void hist_kernel(const int* __restrict__ rows) {
    // int4-vectorized; N_EDGES % 4 == 0 so all 4 lanes share one adjacency
    const int4* r4 = reinterpret_cast<const int4*>(rows);
    int total4 = NADJ * N_EDGES / 4;
    int per_adj4 = N_EDGES / 4;
    for (int i = blockIdx.x * blockDim.x + threadIdx.x; i < total4;
         i += gridDim.x * blockDim.x) {
        int a = i / per_adj4;
        int4 rv = r4[i];
        int* c = g_counts + a * N_NODES;
        atomicAdd(&c[rv.x], 1);
        atomicAdd(&c[rv.y], 1);
        atomicAdd(&c[rv.z], 1);
        atomicAdd(&c[rv.w], 1);
    }
}

__global__ __launch_bounds__(1024) void scan_kernel() {
    // one block per adjacency; each thread owns 20 consecutive counters
    int a = blockIdx.x;
    const int* c = g_counts + a * N_NODES;
    int* s   = g_starts + a * (N_NODES + 1);
    int* cur = g_cursor + a * N_NODES;
    __shared__ int sd[1024];
    int t = threadIdx.x;
    const int PER = 20;
    int base = t * PER;
    int v[PER];
    int lsum = 0;
    #pragma unroll
    for (int i = 0; i < PER; ++i) {
        int idx = base + i;
        v[i] = (idx < N_NODES) ? c[idx] : 0;
        lsum += v[i];
    }
    sd[t] = lsum;
    __syncthreads();
    #pragma unroll
    for (int off = 1; off < 1024; off <<= 1) {
        int x = (t >= off) ? sd[t - off] : 0;
        __syncthreads();
        sd[t] += x;
        __syncthreads();
    }
    int run = sd[t] - lsum;           // exclusive prefix of this thread's chunk
    #pragma unroll
    for (int i = 0; i < PER; ++i) {
        int idx = base + i;
        if (idx < N_NODES) { s[idx] = run; cur[idx] = run; }
        run += v[i];
    }
    if (t == 1023) s[N_NODES] = sd[1023];
}

__global__ void scatter_kernel(const int* __restrict__ rows,
                               const int* __restrict__ cols,
                               const float* __restrict__ vals) {
    const int4*   r4 = reinterpret_cast<const int4*>(rows);
    const int4*   c4 = reinterpret_cast<const int4*>(cols);
    const float4* v4 = reinterpret_cast<const float4*>(vals);
    int total4 = NADJ * N_EDGES / 4;
    int per_adj4 = N_EDGES / 4;
    for (int i = blockIdx.x * blockDim.x + threadIdx.x; i < total4;
         i += gridDim.x * blockDim.x) {
        int a = i / per_adj4;
        int4 rv = r4[i];
        int4 cv = c4[i];
        float4 vv = v4[i];
        int* cur = g_cursor + a * N_NODES;
        int2* perm = g_perm + (size_t)a * N_EDGES;
        int p;
        p = atomicAdd(&cur[rv.x], 1); perm[p] = make_int2(cv.x, __float_as_int(vv.x));
        p = atomicAdd(&cur[rv.y], 1); perm[p] = make_int2(cv.y, __float_as_int(vv.y));
        p = atomicAdd(&cur[rv.z], 1); perm[p] = make_int2(cv.z, __float_as_int(vv.z));
        p = atomicAdd(&cur[rv.w], 1); perm[p] = make_int2(cv.w, __float_as_int(vv.w));
    }
}

// ---------------- GEMM: h = x @ W + b -> fp16 ----------------
#define BM 128
#define BN 128
#define BK 16
__global__ __launch_bounds__(256) void gemm_kernel(const float* __restrict__ X,
                                                   const float* __restrict__ W,
                                                   const float* __restrict__ bias) {
    __shared__ float As[BK][BM];
    __shared__ float Bs[BK][BN];
    int bm = blockIdx.x * BM;
    int bn = blockIdx.y * BN;
    int t  = threadIdx.x;
    int ty = t >> 4;
    int tx = t & 15;
    float acc[8][8];
    #pragma unroll
    for (int i = 0; i < 8; ++i)
        #pragma unroll
        for (int j = 0; j < 8; ++j) acc[i][j] = 0.f;

    for (int k0 = 0; k0 < D; k0 += BK) {
        #pragma unroll
        for (int l = 0; l < 2; ++l) {
            int idx = t + l * 256;
            int row = idx >> 2;
            int vec = idx & 3;
            float4 av = make_float4(0.f, 0.f, 0.f, 0.f);
            int gr = bm + row;
            if (gr < N_NODES)
                av = *reinterpret_cast<const float4*>(X + (size_t)gr * D + k0 + vec * 4);
            As[vec * 4 + 0][row] = av.x;
            As[vec * 4 + 1][row] = av.y;
            As[vec * 4 + 2][row] = av.z;
            As[vec * 4 + 3][row] = av.w;
        }
        #pragma unroll
        for (int l = 0; l < 2; ++l) {
            int idx = t + l * 256;
            int kr  = idx >> 5;
            int vec = idx & 31;
            float4 bv = *reinterpret_cast<const float4*>(W + (size_t)(k0 + kr) * D + bn + vec * 4);
            *reinterpret_cast<float4*>(&Bs[kr][vec * 4]) = bv;
        }
        __syncthreads();
        #pragma unroll
        for (int k = 0; k < BK; ++k) {
            float af[8], bf[8];
            #pragma unroll
            for (int i = 0; i < 8; ++i) af[i] = As[k][ty * 8 + i];
            #pragma unroll
            for (int j = 0; j < 8; ++j) bf[j] = Bs[k][tx * 8 + j];
            #pragma unroll
            for (int i = 0; i < 8; ++i)
                #pragma unroll
                for (int j = 0; j < 8; ++j) acc[i][j] += af[i] * bf[j];
        }
        __syncthreads();
    }
    #pragma unroll
    for (int i = 0; i < 8; ++i) {
        int gr = bm + ty * 8 + i;
        if (gr >= N_NODES) break;
        int gc = bn + tx * 8;
        __half2 h0 = __floats2half2_rn(acc[i][0] + bias[gc + 0], acc[i][1] + bias[gc + 1]);
        __half2 h1 = __floats2half2_rn(acc[i][2] + bias[gc + 2], acc[i][3] + bias[gc + 3]);
        __half2 h2 = __floats2half2_rn(acc[i][4] + bias[gc + 4], acc[i][5] + bias[gc + 5]);
        __half2 h3 = __floats2half2_rn(acc[i][6] + bias[gc + 6], acc[i][7] + bias[gc + 7]);
        uint4 raw;
        raw.x = *reinterpret_cast<unsigned*>(&h0);
        raw.y = *reinterpret_cast<unsigned*>(&h1);
        raw.z = *reinterpret_cast<unsigned*>(&h2);
        raw.w = *reinterpret_cast<unsigned*>(&h3);
        *reinterpret_cast<uint4*>(&g_h16[(size_t)gr * 128 + gc / 2]) = raw;
    }
}

// ---------------- fused SpMM gather kernels (fp16 sources, fp32 accum) ------
__device__ __forceinline__ void gather_adj_h2(int a, int row, int t,
                                              const __half2* __restrict__ src,
                                              int2* sbuf, float4& S) {
    int s = g_starts[a * (N_NODES + 1) + row];
    int e = g_starts[a * (N_NODES + 1) + row + 1];
    S = make_float4(0.f, 0.f, 0.f, 0.f);
    for (int base = s; base < e; base += 64) {
        int m = min(64, e - base);
        if (t < m) sbuf[t] = g_perm[(size_t)a * N_EDGES + base + t];
        __syncthreads();
        #pragma unroll 4
        for (int j = 0; j < m; ++j) {
            int2 cv = sbuf[j];
            float v = __int_as_float(cv.y);
            uint2 raw = reinterpret_cast<const uint2*>(src + (size_t)cv.x * 128)[t];
            float2 f0 = __half22float2(*reinterpret_cast<__half2*>(&raw.x));
            float2 f1 = __half22float2(*reinterpret_cast<__half2*>(&raw.y));
            S.x += v * f0.x; S.y += v * f0.y; S.z += v * f1.x; S.w += v * f1.y;
        }
        __syncthreads();
    }
}

__device__ __forceinline__ void fma4(float4& o, float w, const float4& S) {
    o.x += w * S.x; o.y += w * S.y; o.z += w * S.z; o.w += w * S.w;
}

__device__ __forceinline__ void store_h2(__half2* dst, int row, int t, float4 o) {
    __half2 h0 = __floats2half2_rn(o.x, o.y);
    __half2 h1 = __floats2half2_rn(o.z, o.w);
    uint2 raw;
    raw.x = *reinterpret_cast<unsigned*>(&h0);
    raw.y = *reinterpret_cast<unsigned*>(&h1);
    reinterpret_cast<uint2*>(dst + (size_t)row * 128)[t] = raw;
}

// Kernel A: input s0 (fp16). Produces s1 (fp16), s2 partial (fp32), acc3 partial (fp32).
__global__ __launch_bounds__(64) void kernelA(const float* __restrict__ ws_seq_0,
                                              const float* __restrict__ ws_res_0,
                                              const float* __restrict__ ws_res_1) {
    int row = blockIdx.x;
    int t = threadIdx.x;
    const float k3 = 1.f / 3.f;
    float c0w[4] = { ws_seq_0[0] * k3, ws_seq_0[1] * k3, ws_seq_0[2] * k3, 0.f };
    float c1w[4] = { ws_res_0[0] * 0.25f, ws_res_0[1] * 0.25f, ws_res_0[2] * 0.25f, ws_res_0[3] * 0.25f };
    float c2w[4] = { ws_res_1[0] * k3, ws_res_1[1] * k3, 0.f, ws_res_1[2] * k3 };
    __shared__ int2 sbuf[64];
    float4 o0 = make_float4(0,0,0,0), o1 = o0, o2 = o0;
    #pragma unroll
    for (int a = 0; a < 4; ++a) {
        float4 S;
        gather_adj_h2(a, row, t, g_h16, sbuf, S);
        fma4(o0, c0w[a], S);
        fma4(o1, c1w[a], S);
        fma4(o2, c2w[a], S);
    }
    int off = row * 64 + t;
    store_h2(g_s116, row, t, o0);
    reinterpret_cast<float4*>(g_s2f)[off]  = o1;
    reinterpret_cast<float4*>(g_acc3)[off] = o2;
}

// Kernel B: input s1 (fp16). Finalizes s2 (fp16), accumulates s1 residual into acc3.
__global__ __launch_bounds__(64) void kernelB(const float* __restrict__ ws_seq_0,
                                              const float* __restrict__ ws_res_1) {
    int row = blockIdx.x;
    int t = threadIdx.x;
    const float k3 = 1.f / 3.f;
    float c0w[4] = { ws_seq_0[3] * k3, ws_seq_0[4] * k3, ws_seq_0[5] * k3, 0.f };
    float c1w[4] = { ws_res_1[3] * k3, ws_res_1[4] * k3, 0.f, ws_res_1[5] * k3 };
    __shared__ int2 sbuf[64];
    int off = row * 64 + t;
    float4 o0 = reinterpret_cast<const float4*>(g_s2f)[off];
    float4 o1 = reinterpret_cast<const float4*>(g_acc3)[off];
    #pragma unroll
    for (int a = 0; a < 4; ++a) {
        float4 S;
        gather_adj_h2(a, row, t, g_s116, sbuf, S);
        fma4(o0, c0w[a], S);
        fma4(o1, c1w[a], S);
    }
    store_h2(g_s216, row, t, o0);
    reinterpret_cast<float4*>(g_acc3)[off] = o1;
}

// Kernel C: input s2 (fp16, adjacencies 0,1). Adds acc3, LayerNorm + exact GELU.
__global__ __launch_bounds__(64) void kernelC(const float* __restrict__ ws_seq_1,
                                              float* __restrict__ out) {
    int row = blockIdx.x;
    int t = threadIdx.x;
    float cw[2] = { ws_seq_1[0] * 0.5f, ws_seq_1[1] * 0.5f };
    __shared__ int2 sbuf[64];
    __shared__ float ssum[2], ssq[2];
    int off = row * 64 + t;
    float4 o = reinterpret_cast<const float4*>(g_acc3)[off];
    #pragma unroll
    for (int a = 0; a < 2; ++a) {
        float4 S;
        gather_adj_h2(a, row, t, g_s216, sbuf, S);
        fma4(o, cw[a], S);
    }
    float sum = o.x + o.y + o.z + o.w;
    float sq  = o.x * o.x + o.y * o.y + o.z * o.z + o.w * o.w;
    #pragma unroll
    for (int d = 16; d > 0; d >>= 1) {
        sum += __shfl_xor_sync(0xffffffffu, sum, d);
        sq  += __shfl_xor_sync(0xffffffffu, sq,  d);
    }
    int wid = t >> 5;
    if ((t & 31) == 0) { ssum[wid] = sum; ssq[wid] = sq; }
    __syncthreads();
    sum = ssum[0] + ssum[1];
    sq  = ssq[0]  + ssq[1];
    float mu  = sum * (1.f / 256.f);
    float var = sq * (1.f / 256.f) - mu * mu;
    float inv = rsqrtf(var + LN_EPS);
    float4 r;
    {
        float y;
        y = (o.x - mu) * inv; r.x = 0.5f * y * (1.f + erff(y * 0.70710678118654752f));
        y = (o.y - mu) * inv; r.y = 0.5f * y * (1.f + erff(y * 0.70710678118654752f));
        y = (o.z - mu) * inv; r.z = 0.5f * y * (1.f + erff(y * 0.70710678118654752f));
        y = (o.w - mu) * inv; r.w = 0.5f * y * (1.f + erff(y * 0.70710678118654752f));
    }
    reinterpret_cast<float4*>(out)[off] = r;
}

// ---------------- launch ----------------
extern "C" void kernel_launch(void* const* d_in, const int* in_sizes, int n_in,
                              void* d_out, int out_size) {
    const float* x        = (const float*)d_in[0];
    const int*   rows     = (const int*)  d_in[1];
    const int*   cols     = (const int*)  d_in[2];
    const float* vals     = (const float*)d_in[3];
    const float* W        = (const float*)d_in[4];
    const float* b        = (const float*)d_in[5];
    const float* ws_seq_0 = (const float*)d_in[6];
    const float* ws_seq_1 = (const float*)d_in[7];
    const float* ws_res_0 = (const float*)d_in[8];
    const float* ws_res_1 = (const float*)d_in[9];
    float* out = (float*)d_out;

    // one-time stream/event setup (host-side resources only; no device memory)
    static cudaStream_t st_gemm = nullptr;
    static cudaEvent_t  ev_root = nullptr, ev_gemm = nullptr;
    if (st_gemm == nullptr) {
        cudaStreamCreateWithFlags(&st_gemm, cudaStreamNonBlocking);
        cudaEventCreateWithFlags(&ev_root, cudaEventDisableTiming);
        cudaEventCreateWithFlags(&ev_gemm, cudaEventDisableTiming);
    }

    // fork: GEMM runs concurrently with the CSR build
    cudaEventRecord(ev_root, 0);
    cudaStreamWaitEvent(st_gemm, ev_root, 0);
    gemm_kernel<<<dim3((N_NODES + BM - 1) / BM, D / BN), 256, 0, st_gemm>>>(x, W, b);
    cudaEventRecord(ev_gemm, st_gemm);

    // CSR build on the main (captured) stream
    zero_counts_kernel<<<(NADJ * N_NODES + 255) / 256, 256>>>();
    hist_kernel<<<296, 256>>>(rows);
    scan_kernel<<<4, 1024>>>();
    scatter_kernel<<<296, 256>>>(rows, cols, vals);

    // join, then the three fused gather stages
    cudaStreamWaitEvent(0, ev_gemm, 0);
    kernelA<<<N_NODES, 64>>>(ws_seq_0, ws_res_0, ws_res_1);
    kernelB<<<N_NODES, 64>>>(ws_seq_0, ws_res_1);
    kernelC<<<N_NODES, 64>>>(ws_seq_1, out);
}

// round 3
// speedup vs baseline: 1.5590x; 1.1907x over previous
#include <cuda_runtime.h>
#include <cuda_fp16.h>
#include <mma.h>
#include <math.h>

using namespace nvcuda;

#define N_NODES 20000
#define N_EDGES 320000
#define D 256
#define NADJ 4
#define LN_EPS 1e-5f
#define NCHUNK 20          // scan chunks per adjacency (1000 nodes each)

// ---------------- scratch (device globals; no allocation) ----------------
__device__ __half2 g_x16 [N_NODES * 128];   // x   (fp16)
__device__ __half2 g_W16 [D * 128];         // W   (fp16)
__device__ __half2 g_h16 [N_NODES * 128];   // s0 = xW + b   (fp16)
__device__ __half2 g_s116[N_NODES * 128];   // state 1       (fp16)
__device__ __half2 g_s216[N_NODES * 128];   // state 2 final (fp16)
__device__ float   g_s2f [N_NODES * D];     // s2 fp32 partial (s0 residual)
__device__ float   g_acc3[N_NODES * D];     // out-residual fp32 accumulator
__device__ int     g_counts[NADJ * N_NODES];
__device__ int     g_starts[NADJ * (N_NODES + 1)];
__device__ int     g_cursor[NADJ * N_NODES];
__device__ int     g_chunksum[NADJ * NCHUNK];
__device__ int     g_chunkoff[NADJ * NCHUNK];
__device__ int2    g_perm  [NADJ * N_EDGES];   // (col, val-as-bits), CSR-permuted

// ---------------- CSR build ----------------
__global__ void zero_counts_kernel() {
    int i = blockIdx.x * blockDim.x + threadIdx.x;
    if (i < NADJ * N_NODES) g_counts[i] = 0;
}

__global__ void hist_kernel(const int* __restrict__ rows) {
    const int4* r4 = reinterpret_cast<const int4*>(rows);
    int total4 = NADJ * N_EDGES / 4;
    int per_adj4 = N_EDGES / 4;
    for (int i = blockIdx.x * blockDim.x + threadIdx.x; i < total4;
         i += gridDim.x * blockDim.x) {
        int a = i / per_adj4;
        int4 rv = r4[i];
        int* c = g_counts + a * N_NODES;
        atomicAdd(&c[rv.x], 1);
        atomicAdd(&c[rv.y], 1);
        atomicAdd(&c[rv.z], 1);
        atomicAdd(&c[rv.w], 1);
    }
}

// stage 1: per-chunk sums (4 adj x 20 chunks of 1000 nodes)
__global__ __launch_bounds__(256) void scan1_kernel() {
    int blk = blockIdx.x;                    // 0..79
    int base = blk * 1000;                   // contiguous in g_counts (adj-major)
    int t = threadIdx.x;
    int v = 0;
    for (int i = t; i < 1000; i += 256) v += g_counts[base + i];
    __shared__ int sd[256];
    sd[t] = v;
    __syncthreads();
    #pragma unroll
    for (int off = 128; off > 0; off >>= 1) {
        if (t < off) sd[t] += sd[t + off];
        __syncthreads();
    }
    if (t == 0) g_chunksum[blk] = sd[0];
}

// stage 2: segmented exclusive scan of 20 chunk sums per adjacency (trivial)
__global__ void scan2_kernel() {
    int a = threadIdx.x;
    if (a < NADJ) {
        int run = 0;
        for (int c = 0; c < NCHUNK; ++c) {
            g_chunkoff[a * NCHUNK + c] = run;
            run += g_chunksum[a * NCHUNK + c];
        }
    }
}

// stage 3: per-chunk scan with global offset -> starts + cursor
__global__ __launch_bounds__(256) void scan3_kernel() {
    int blk = blockIdx.x;                    // 0..79
    int a = blk / NCHUNK;
    int base = blk * 1000;                   // index into g_counts (adj-major flat)
    int node0 = base - a * N_NODES;          // node index within adjacency
    int t = threadIdx.x;
    const int PER = 4;                       // 256*4 = 1024 >= 1000
    int v[PER];
    int lsum = 0;
    #pragma unroll
    for (int i = 0; i < PER; ++i) {
        int idx = t * PER + i;
        v[i] = (idx < 1000) ? g_counts[base + idx] : 0;
        lsum += v[i];
    }
    __shared__ int sd[256];
    sd[t] = lsum;
    __syncthreads();
    #pragma unroll
    for (int off = 1; off < 256; off <<= 1) {
        int x = (t >= off) ? sd[t - off] : 0;
        __syncthreads();
        sd[t] += x;
        __syncthreads();
    }
    int run = g_chunkoff[blk] + sd[t] - lsum;
    int* s   = g_starts + a * (N_NODES + 1) + node0;
    int* cur = g_cursor + a * N_NODES + node0;
    #pragma unroll
    for (int i = 0; i < PER; ++i) {
        int idx = t * PER + i;
        if (idx < 1000) { s[idx] = run; cur[idx] = run; }
        run += v[i];
    }
    if (blk % NCHUNK == NCHUNK - 1 && t == 255)
        g_starts[a * (N_NODES + 1) + N_NODES] = N_EDGES;
}

__global__ void scatter_kernel(const int* __restrict__ rows,
                               const int* __restrict__ cols,
                               const float* __restrict__ vals) {
    const int4*   r4 = reinterpret_cast<const int4*>(rows);
    const int4*   c4 = reinterpret_cast<const int4*>(cols);
    const float4* v4 = reinterpret_cast<const float4*>(vals);
    int total4 = NADJ * N_EDGES / 4;
    int per_adj4 = N_EDGES / 4;
    for (int i = blockIdx.x * blockDim.x + threadIdx.x; i < total4;
         i += gridDim.x * blockDim.x) {
        int a = i / per_adj4;
        int4 rv = r4[i];
        int4 cv = c4[i];
        float4 vv = v4[i];
        int* cur = g_cursor + a * N_NODES;
        int2* perm = g_perm + (size_t)a * N_EDGES;
        int p;
        p = atomicAdd(&cur[rv.x], 1); perm[p] = make_int2(cv.x, __float_as_int(vv.x));
        p = atomicAdd(&cur[rv.y], 1); perm[p] = make_int2(cv.y, __float_as_int(vv.y));
        p = atomicAdd(&cur[rv.z], 1); perm[p] = make_int2(cv.z, __float_as_int(vv.z));
        p = atomicAdd(&cur[rv.w], 1); perm[p] = make_int2(cv.w, __float_as_int(vv.w));
    }
}

// ---------------- fp32 -> fp16 converts ----------------
__global__ void convert_x_kernel(const float* __restrict__ X) {
    int i = blockIdx.x * blockDim.x + threadIdx.x;     // one float4 -> 2 half2
    int total = N_NODES * 64;                          // float4 count
    if (i < total) {
        float4 v = reinterpret_cast<const float4*>(X)[i];
        __half2 h0 = __floats2half2_rn(v.x, v.y);
        __half2 h1 = __floats2half2_rn(v.z, v.w);
        uint2 raw;
        raw.x = *reinterpret_cast<unsigned*>(&h0);
        raw.y = *reinterpret_cast<unsigned*>(&h1);
        reinterpret_cast<uint2*>(g_x16)[i] = raw;
    }
}

__global__ void convert_W_kernel(const float* __restrict__ W) {
    int i = blockIdx.x * blockDim.x + threadIdx.x;
    int total = D * 64;
    if (i < total) {
        float4 v = reinterpret_cast<const float4*>(W)[i];
        __half2 h0 = __floats2half2_rn(v.x, v.y);
        __half2 h1 = __floats2half2_rn(v.z, v.w);
        uint2 raw;
        raw.x = *reinterpret_cast<unsigned*>(&h0);
        raw.y = *reinterpret_cast<unsigned*>(&h1);
        reinterpret_cast<uint2*>(g_W16)[i] = raw;
    }
}

// ---------------- wmma GEMM: h = x @ W + b (fp16 in, fp32 acc, fp16 out) ----
#define GBM 64
#define GBN 64
#define ALD 24     // As leading dim (halves), 48B multiple of 16B
#define BLD 72     // Bs leading dim (halves), 144B multiple of 16B
__global__ __launch_bounds__(128) void gemm_wmma_kernel(const float* __restrict__ bias) {
    __shared__ __half As[GBM * ALD];
    __shared__ __half Bs[16 * BLD];
    __shared__ float  Cst[GBM * GBN];
    int bm = blockIdx.x * GBM;
    int bn = blockIdx.y * GBN;
    int t  = threadIdx.x;
    int warp = t >> 5;
    int wm = warp >> 1;      // 0..1 : row block of 32
    int wn = warp & 1;       // 0..1 : col block of 32

    wmma::fragment<wmma::accumulator, 16, 16, 16, float> c[2][2];
    #pragma unroll
    for (int i = 0; i < 2; ++i)
        #pragma unroll
        for (int j = 0; j < 2; ++j) wmma::fill_fragment(c[i][j], 0.f);

    for (int k0 = 0; k0 < D; k0 += 16) {
        // load A tile 64x16 halves: 128 uint4 (8 halves each)
        {
            int row = t >> 1;
            int part = t & 1;
            uint4 raw = make_uint4(0, 0, 0, 0);
            int gr = bm + row;
            if (gr < N_NODES)
                raw = *reinterpret_cast<const uint4*>(&g_x16[(size_t)gr * 128 + k0 / 2 + part * 4]);
            *reinterpret_cast<uint4*>(&As[row * ALD + part * 8]) = raw;
        }
        // load B tile 16x64 halves: 128 uint4
        {
            int r = t >> 3;
            int part = t & 7;
            uint4 raw = *reinterpret_cast<const uint4*>(&g_W16[(size_t)(k0 + r) * 128 + bn / 2 + part * 4]);
            *reinterpret_cast<uint4*>(&Bs[r * BLD + part * 8]) = raw;
        }
        __syncthreads();
        wmma::fragment<wmma::matrix_a, 16, 16, 16, __half, wmma::row_major> a[2];
        wmma::fragment<wmma::matrix_b, 16, 16, 16, __half, wmma::row_major> bfr[2];
        #pragma unroll
        for (int i = 0; i < 2; ++i)
            wmma::load_matrix_sync(a[i], As + (wm * 32 + i * 16) * ALD, ALD);
        #pragma unroll
        for (int j = 0; j < 2; ++j)
            wmma::load_matrix_sync(bfr[j], Bs + wn * 32 + j * 16, BLD);
        #pragma unroll
        for (int i = 0; i < 2; ++i)
            #pragma unroll
            for (int j = 0; j < 2; ++j)
                wmma::mma_sync(c[i][j], a[i], bfr[j], c[i][j]);
        __syncthreads();
    }
    #pragma unroll
    for (int i = 0; i < 2; ++i)
        #pragma unroll
        for (int j = 0; j < 2; ++j)
            wmma::store_matrix_sync(Cst + (wm * 32 + i * 16) * GBN + wn * 32 + j * 16,
                                    c[i][j], GBN, wmma::mem_row_major);
    __syncthreads();
    // epilogue: +bias, fp16 pack, store
    {
        int row = t >> 1;
        int half_side = t & 1;
        int gr = bm + row;
        if (gr < N_NODES) {
            int gc0 = bn + half_side * 32;
            const float* crow = Cst + row * GBN + half_side * 32;
            #pragma unroll
            for (int q = 0; q < 4; ++q) {
                __half2 hh[4];
                #pragma unroll
                for (int j = 0; j < 4; ++j) {
                    int cc = q * 8 + 2 * j;
                    hh[j] = __floats2half2_rn(crow[cc] + bias[gc0 + cc],
                                              crow[cc + 1] + bias[gc0 + cc + 1]);
                }
                uint4 raw;
                raw.x = *reinterpret_cast<unsigned*>(&hh[0]);
                raw.y = *reinterpret_cast<unsigned*>(&hh[1]);
                raw.z = *reinterpret_cast<unsigned*>(&hh[2]);
                raw.w = *reinterpret_cast<unsigned*>(&hh[3]);
                *reinterpret_cast<uint4*>(&g_h16[(size_t)gr * 128 + gc0 / 2 + q * 4]) = raw;
            }
        }
    }
}

// ---------------- fused SpMM gather kernels (fp16 sources, fp32 accum) ------
__device__ __forceinline__ void gather_adj_h2(int a, int row, int t,
                                              const __half2* __restrict__ src,
                                              int2* sbuf, float4& S) {
    int s = g_starts[a * (N_NODES + 1) + row];
    int e = g_starts[a * (N_NODES + 1) + row + 1];
    S = make_float4(0.f, 0.f, 0.f, 0.f);
    for (int base = s; base < e; base += 64) {
        int m = min(64, e - base);
        if (t < m) sbuf[t] = g_perm[(size_t)a * N_EDGES + base + t];
        __syncthreads();
        #pragma unroll 4
        for (int j = 0; j < m; ++j) {
            int2 cv = sbuf[j];
            float v = __int_as_float(cv.y);
            uint2 raw = reinterpret_cast<const uint2*>(src + (size_t)cv.x * 128)[t];
            float2 f0 = __half22float2(*reinterpret_cast<__half2*>(&raw.x));
            float2 f1 = __half22float2(*reinterpret_cast<__half2*>(&raw.y));
            S.x += v * f0.x; S.y += v * f0.y; S.z += v * f1.x; S.w += v * f1.y;
        }
        __syncthreads();
    }
}

__device__ __forceinline__ void fma4(float4& o, float w, const float4& S) {
    o.x += w * S.x; o.y += w * S.y; o.z += w * S.z; o.w += w * S.w;
}

__device__ __forceinline__ void store_h2(__half2* dst, int row, int t, float4 o) {
    __half2 h0 = __floats2half2_rn(o.x, o.y);
    __half2 h1 = __floats2half2_rn(o.z, o.w);
    uint2 raw;
    raw.x = *reinterpret_cast<unsigned*>(&h0);
    raw.y = *reinterpret_cast<unsigned*>(&h1);
    reinterpret_cast<uint2*>(dst + (size_t)row * 128)[t] = raw;
}

__global__ __launch_bounds__(64) void kernelA(const float* __restrict__ ws_seq_0,
                                              const float* __restrict__ ws_res_0,
                                              const float* __restrict__ ws_res_1) {
    int row = blockIdx.x;
    int t = threadIdx.x;
    const float k3 = 1.f / 3.f;
    float c0w[4] = { ws_seq_0[0] * k3, ws_seq_0[1] * k3, ws_seq_0[2] * k3, 0.f };
    float c1w[4] = { ws_res_0[0] * 0.25f, ws_res_0[1] * 0.25f, ws_res_0[2] * 0.25f, ws_res_0[3] * 0.25f };
    float c2w[4] = { ws_res_1[0] * k3, ws_res_1[1] * k3, 0.f, ws_res_1[2] * k3 };
    __shared__ int2 sbuf[64];
    float4 o0 = make_float4(0,0,0,0), o1 = o0, o2 = o0;
    #pragma unroll
    for (int a = 0; a < 4; ++a) {
        float4 S;
        gather_adj_h2(a, row, t, g_h16, sbuf, S);
        fma4(o0, c0w[a], S);
        fma4(o1, c1w[a], S);
        fma4(o2, c2w[a], S);
    }
    int off = row * 64 + t;
    store_h2(g_s116, row, t, o0);
    reinterpret_cast<float4*>(g_s2f)[off]  = o1;
    reinterpret_cast<float4*>(g_acc3)[off] = o2;
}

__global__ __launch_bounds__(64) void kernelB(const float* __restrict__ ws_seq_0,
                                              const float* __restrict__ ws_res_1) {
    int row = blockIdx.x;
    int t = threadIdx.x;
    const float k3 = 1.f / 3.f;
    float c0w[4] = { ws_seq_0[3] * k3, ws_seq_0[4] * k3, ws_seq_0[5] * k3, 0.f };
    float c1w[4] = { ws_res_1[3] * k3, ws_res_1[4] * k3, 0.f, ws_res_1[5] * k3 };
    __shared__ int2 sbuf[64];
    int off = row * 64 + t;
    float4 o0 = reinterpret_cast<const float4*>(g_s2f)[off];
    float4 o1 = reinterpret_cast<const float4*>(g_acc3)[off];
    #pragma unroll
    for (int a = 0; a < 4; ++a) {
        float4 S;
        gather_adj_h2(a, row, t, g_s116, sbuf, S);
        fma4(o0, c0w[a], S);
        fma4(o1, c1w[a], S);
    }
    store_h2(g_s216, row, t, o0);
    reinterpret_cast<float4*>(g_acc3)[off] = o1;
}

__global__ __launch_bounds__(64) void kernelC(const float* __restrict__ ws_seq_1,
                                              float* __restrict__ out) {
    int row = blockIdx.x;
    int t = threadIdx.x;
    float cw[2] = { ws_seq_1[0] * 0.5f, ws_seq_1[1] * 0.5f };
    __shared__ int2 sbuf[64];
    __shared__ float ssum[2], ssq[2];
    int off = row * 64 + t;
    float4 o = reinterpret_cast<const float4*>(g_acc3)[off];
    #pragma unroll
    for (int a = 0; a < 2; ++a) {
        float4 S;
        gather_adj_h2(a, row, t, g_s216, sbuf, S);
        fma4(o, cw[a], S);
    }
    float sum = o.x + o.y + o.z + o.w;
    float sq  = o.x * o.x + o.y * o.y + o.z * o.z + o.w * o.w;
    #pragma unroll
    for (int d = 16; d > 0; d >>= 1) {
        sum += __shfl_xor_sync(0xffffffffu, sum, d);
        sq  += __shfl_xor_sync(0xffffffffu, sq,  d);
    }
    int wid = t >> 5;
    if ((t & 31) == 0) { ssum[wid] = sum; ssq[wid] = sq; }
    __syncthreads();
    sum = ssum[0] + ssum[1];
    sq  = ssq[0]  + ssq[1];
    float mu  = sum * (1.f / 256.f);
    float var = sq * (1.f / 256.f) - mu * mu;
    float inv = rsqrtf(var + LN_EPS);
    float4 r;
    {
        float y;
        y = (o.x - mu) * inv; r.x = 0.5f * y * (1.f + erff(y * 0.70710678118654752f));
        y = (o.y - mu) * inv; r.y = 0.5f * y * (1.f + erff(y * 0.70710678118654752f));
        y = (o.z - mu) * inv; r.z = 0.5f * y * (1.f + erff(y * 0.70710678118654752f));
        y = (o.w - mu) * inv; r.w = 0.5f * y * (1.f + erff(y * 0.70710678118654752f));
    }
    reinterpret_cast<float4*>(out)[off] = r;
}

// ---------------- launch ----------------
extern "C" void kernel_launch(void* const* d_in, const int* in_sizes, int n_in,
                              void* d_out, int out_size) {
    const float* x        = (const float*)d_in[0];
    const int*   rows     = (const int*)  d_in[1];
    const int*   cols     = (const int*)  d_in[2];
    const float* vals     = (const float*)d_in[3];
    const float* W        = (const float*)d_in[4];
    const float* b        = (const float*)d_in[5];
    const float* ws_seq_0 = (const float*)d_in[6];
    const float* ws_seq_1 = (const float*)d_in[7];
    const float* ws_res_0 = (const float*)d_in[8];
    const float* ws_res_1 = (const float*)d_in[9];
    float* out = (float*)d_out;

    static cudaStream_t st_gemm = nullptr;
    static cudaEvent_t  ev_root = nullptr, ev_gemm = nullptr;
    if (st_gemm == nullptr) {
        cudaStreamCreateWithFlags(&st_gemm, cudaStreamNonBlocking);
        cudaEventCreateWithFlags(&ev_root, cudaEventDisableTiming);
        cudaEventCreateWithFlags(&ev_gemm, cudaEventDisableTiming);
    }

    // fork: convert + tensor-core GEMM concurrently with the CSR build
    cudaEventRecord(ev_root, 0);
    cudaStreamWaitEvent(st_gemm, ev_root, 0);
    convert_x_kernel<<<(N_NODES * 64 + 255) / 256, 256, 0, st_gemm>>>(x);
    convert_W_kernel<<<(D * 64 + 255) / 256, 256, 0, st_gemm>>>(W);
    gemm_wmma_kernel<<<dim3((N_NODES + GBM - 1) / GBM, D / GBN), 128, 0, st_gemm>>>(b);
    cudaEventRecord(ev_gemm, st_gemm);

    // CSR build on the main (captured) stream
    zero_counts_kernel<<<(NADJ * N_NODES + 255) / 256, 256>>>();
    hist_kernel<<<296, 256>>>(rows);
    scan1_kernel<<<NADJ * NCHUNK, 256>>>();
    scan2_kernel<<<1, 32>>>();
    scan3_kernel<<<NADJ * NCHUNK, 256>>>();
    scatter_kernel<<<296, 256>>>(rows, cols, vals);

    // join, then the three fused gather stages
    cudaStreamWaitEvent(0, ev_gemm, 0);
    kernelA<<<N_NODES, 64>>>(ws_seq_0, ws_res_0, ws_res_1);
    kernelB<<<N_NODES, 64>>>(ws_seq_0, ws_res_1);
    kernelC<<<N_NODES, 64>>>(ws_seq_1, out);
}